// round 7
// baseline (speedup 1.0000x reference)
#include <cuda_runtime.h>
#include <cuda_bf16.h>
#include <mma.h>

using namespace nvcuda;

#define B_    8
#define N_    256
#define C_    512
#define HW_   64
#define DIM_  1024
#define M_    (B_ * N_)          // 2048

// ---------------- device scratch (no allocation allowed) -------------------
__device__ float g_z[M_ * DIM_];   // unscaled projections: A matrix of the GEMM (8 MB)
__device__ float g_msum[M_];       // per-(b,n) sum over (C,H,W)
__device__ float g_s[M_];          // a1*a2*a3 per (b,n)
__device__ float g_cvec[DIM_];     // bs_vec @ fc_w^T + fc_b

// ===========================================================================
// K1: single fused pass over x (256 MB, read exactly once).
// Half-warp (16 lanes x float4 = 64 floats = one channel slab, 256B coalesced).
// Each warp covers 2 channels; block = 8 warps = 16 channels/iter, 32 iters.
// Ws (2 float4 per lane) amortized over NT=4 consecutive n values.
// Emits z[m][2c],z[m][2c+1] and accumulates msum via deterministic reduction.
// ===========================================================================
__global__ __launch_bounds__(256)
void k_reduce(const float4* __restrict__ x4, const float4* __restrict__ Ws4)
{
    const int m0   = blockIdx.x * 4;          // 512 blocks -> m = b*256+n
    const int tid  = threadIdx.x;
    const int warp = tid >> 5;
    const int lane = tid & 31;
    const int half = lane >> 4;               // which channel within the warp
    const int hl   = lane & 15;               // lane within half-warp

    float sum0 = 0.f, sum1 = 0.f, sum2 = 0.f, sum3 = 0.f;

    #pragma unroll 1
    for (int it = 0; it < 32; ++it) {
        const int c = it * 16 + warp * 2 + half;
        // Ws: [c][o][64] floats -> float4 index c*32 + o*16 + hl
        const float4 w0 = Ws4[c * 32 + hl];
        const float4 w1 = Ws4[c * 32 + 16 + hl];

        #pragma unroll
        for (int nt = 0; nt < 4; ++nt) {
            const int m  = m0 + nt;
            const float4 xv = x4[(m * C_ + c) * 16 + hl];
            float z0 = xv.x * w0.x + xv.y * w0.y + xv.z * w0.z + xv.w * w0.w;
            float z1 = xv.x * w1.x + xv.y * w1.y + xv.z * w1.z + xv.w * w1.w;
            const float ls = (xv.x + xv.y) + (xv.z + xv.w);
            if (nt == 0) sum0 += ls; else if (nt == 1) sum1 += ls;
            else if (nt == 2) sum2 += ls; else sum3 += ls;
            // butterfly reduce over the 16-lane half (xor 8,4,2,1 stays in-half)
            #pragma unroll
            for (int off = 8; off; off >>= 1) {
                z0 += __shfl_xor_sync(0xffffffffu, z0, off);
                z1 += __shfl_xor_sync(0xffffffffu, z1, off);
            }
            if (hl == 0)
                *(float2*)&g_z[m * DIM_ + 2 * c] = make_float2(z0, z1);
        }
    }

    // deterministic block reduction of the 4 per-n partial sums
    #pragma unroll
    for (int off = 16; off; off >>= 1) {
        sum0 += __shfl_xor_sync(0xffffffffu, sum0, off);
        sum1 += __shfl_xor_sync(0xffffffffu, sum1, off);
        sum2 += __shfl_xor_sync(0xffffffffu, sum2, off);
        sum3 += __shfl_xor_sync(0xffffffffu, sum3, off);
    }
    __shared__ float red[8][4];
    if (lane == 0) {
        red[warp][0] = sum0; red[warp][1] = sum1;
        red[warp][2] = sum2; red[warp][3] = sum3;
    }
    __syncthreads();
    if (tid < 4) {
        float t = 0.f;
        #pragma unroll
        for (int w = 0; w < 8; ++w) t += red[w][tid];
        g_msum[m0 + tid] = t;
    }
}

// ===========================================================================
// K2: attention chain on the 2048-element mean vector. One block per b.
// ===========================================================================
__global__ __launch_bounds__(256)
void k_att(const float* __restrict__ conv_w, const float* __restrict__ conv_b)
{
    const int b = blockIdx.x;
    const int n = threadIdx.x;
    __shared__ float sm_m[N_];
    sm_m[n] = g_msum[b * N_ + n] * (1.0f / 32768.0f);   // mean over C*H*W
    float stot = 1.f;
    #pragma unroll
    for (int i = 0; i < 3; ++i) {
        __syncthreads();
        float acc = conv_b[i];
        #pragma unroll
        for (int j = 0; j < 5; ++j) {
            const int idx = n + j - 2;
            const float v = (idx >= 0 && idx < N_) ? sm_m[idx] : 0.f;
            acc += v * conv_w[i * 5 + j];
        }
        const float att = 1.0f / (1.0f + __expf(-acc));
        stot *= att;
        __syncthreads();
        sm_m[n] *= att;
    }
    g_s[b * N_ + n] = stot;
}

// ===========================================================================
// K3: cvec[d] = sum_k bs_vec[k]*fc_w[d,k] + fc_b[d]. One warp per d.
// bs is [C,2] row-major => flattened index == k = 2c+o. fc_w row-major [d][k].
// ===========================================================================
__global__ __launch_bounds__(256)
void k_cvec(const float* __restrict__ bs, const float* __restrict__ fc_w,
            const float* __restrict__ fc_b)
{
    const int gw   = (blockIdx.x * blockDim.x + threadIdx.x) >> 5;  // d
    const int lane = threadIdx.x & 31;
    float acc = 0.f;
    for (int k = lane; k < DIM_; k += 32)
        acc += bs[k] * fc_w[gw * DIM_ + k];
    #pragma unroll
    for (int off = 16; off; off >>= 1)
        acc += __shfl_xor_sync(0xffffffffu, acc, off);
    if (lane == 0) g_cvec[gw] = acc + fc_b[gw];
}

// ===========================================================================
// K4: out[m,d] = s[m] * sum_k z[m,k]*fc_w[d,k] + cvec[d]
// tf32 wmma m16n16k8. CTA tile 128x128, BK=32, double-buffered smem,
// 8 warps as 2x4 (warp tile 64x32 = 4x2 wmma tiles). Epilogue through smem.
// ===========================================================================
#define BM   128
#define BN   128
#define BK   32
#define LDA  36     // BK + 4 pad
#define LDC  132    // BN + 4 pad

__global__ __launch_bounds__(256)
void k_gemm(const float* __restrict__ fc_w, float* __restrict__ out)
{
    extern __shared__ float sm[];
    float* As = sm;                       // [2][BM][LDA]
    float* Bs = sm + 2 * BM * LDA;        // [2][BN][LDA]

    const int tid  = threadIdx.x;
    const int warp = tid >> 5;
    const int wm   = warp >> 2;           // 0..1
    const int wn   = warp & 3;            // 0..3
    const int m_cta = blockIdx.y * BM;    // 16
    const int n_cta = blockIdx.x * BN;    // 8

    wmma::fragment<wmma::accumulator, 16, 16, 8, float> acc[4][2];
    #pragma unroll
    for (int i = 0; i < 4; ++i)
        #pragma unroll
        for (int j = 0; j < 2; ++j)
            wmma::fill_fragment(acc[i][j], 0.0f);

    // staging: each thread moves 4 float4 of A and 4 float4 of B per stage
    const int row = (tid >> 3);           // base row for r=0 (stride 32 rows)
    const int cg  = (tid & 7) * 4;        // float4 column group

    float4 ra[4], rb[4];
    // prologue: load k0 = 0
    #pragma unroll
    for (int r = 0; r < 4; ++r) {
        const int rw = row + r * 32;
        ra[r] = *(const float4*)&g_z[(m_cta + rw) * DIM_ + cg];
        rb[r] = *(const float4*)&fc_w[(n_cta + rw) * DIM_ + cg];
    }

    const int NSTAGE = DIM_ / BK;         // 32
    #pragma unroll 1
    for (int t = 0; t < NSTAGE; ++t) {
        const int s = t & 1;
        // commit current regs -> buffer s (tf32-convert once here)
        #pragma unroll
        for (int r = 0; r < 4; ++r) {
            const int rw = row + r * 32;
            float* pa = &As[s * BM * LDA + rw * LDA + cg];
            float* pb = &Bs[s * BN * LDA + rw * LDA + cg];
            pa[0] = wmma::__float_to_tf32(ra[r].x);
            pa[1] = wmma::__float_to_tf32(ra[r].y);
            pa[2] = wmma::__float_to_tf32(ra[r].z);
            pa[3] = wmma::__float_to_tf32(ra[r].w);
            pb[0] = wmma::__float_to_tf32(rb[r].x);
            pb[1] = wmma::__float_to_tf32(rb[r].y);
            pb[2] = wmma::__float_to_tf32(rb[r].z);
            pb[3] = wmma::__float_to_tf32(rb[r].w);
        }
        __syncthreads();
        // prefetch next stage into registers (hidden under the mma work)
        if (t + 1 < NSTAGE) {
            const int k0 = (t + 1) * BK;
            #pragma unroll
            for (int r = 0; r < 4; ++r) {
                const int rw = row + r * 32;
                ra[r] = *(const float4*)&g_z[(m_cta + rw) * DIM_ + k0 + cg];
                rb[r] = *(const float4*)&fc_w[(n_cta + rw) * DIM_ + k0 + cg];
            }
        }
        // compute on buffer s
        #pragma unroll
        for (int kk = 0; kk < BK; kk += 8) {
            wmma::fragment<wmma::matrix_a, 16, 16, 8, wmma::precision::tf32, wmma::row_major> af[4];
            wmma::fragment<wmma::matrix_b, 16, 16, 8, wmma::precision::tf32, wmma::col_major> bf[2];
            #pragma unroll
            for (int i = 0; i < 4; ++i)
                wmma::load_matrix_sync(af[i], &As[s * BM * LDA + (wm * 64 + i * 16) * LDA + kk], LDA);
            #pragma unroll
            for (int j = 0; j < 2; ++j)
                wmma::load_matrix_sync(bf[j], &Bs[s * BN * LDA + (wn * 32 + j * 16) * LDA + kk], LDA);
            #pragma unroll
            for (int i = 0; i < 4; ++i)
                #pragma unroll
                for (int j = 0; j < 2; ++j)
                    wmma::mma_sync(acc[i][j], af[i], bf[j], acc[i][j]);
        }
        __syncthreads();
    }

    // epilogue: stage accumulators through smem, then scaled coalesced store
    float* Cs = sm;                       // reuse: 128*132*4 = 67.6 KB
    #pragma unroll
    for (int i = 0; i < 4; ++i)
        #pragma unroll
        for (int j = 0; j < 2; ++j)
            wmma::store_matrix_sync(&Cs[(wm * 64 + i * 16) * LDC + wn * 32 + j * 16],
                                    acc[i][j], LDC, wmma::mem_row_major);
    __syncthreads();

    #pragma unroll
    for (int r = 0; r < 16; ++r) {
        const int idx = tid + r * 256;    // 0..4095
        const int rw  = idx >> 5;         // row 0..127
        const int cc  = (idx & 31) * 4;   // col group
        const float4 cv = *(const float4*)&Cs[rw * LDC + cc];
        const float4 bv = *(const float4*)&g_cvec[n_cta + cc];
        const float  sc = g_s[m_cta + rw];
        float4 o;
        o.x = sc * cv.x + bv.x;
        o.y = sc * cv.y + bv.y;
        o.z = sc * cv.z + bv.z;
        o.w = sc * cv.w + bv.w;
        *(float4*)&out[(m_cta + rw) * DIM_ + n_cta + cc] = o;
    }
}

// ===========================================================================
extern "C" void kernel_launch(void* const* d_in, const int* in_sizes, int n_in,
                              void* d_out, int out_size)
{
    (void)in_sizes; (void)n_in; (void)out_size;
    const float* x      = (const float*)d_in[0];
    const float* conv_w = (const float*)d_in[1];
    const float* conv_b = (const float*)d_in[2];
    const float* Ws     = (const float*)d_in[3];
    const float* bs     = (const float*)d_in[4];
    const float* fc_w   = (const float*)d_in[5];
    const float* fc_b   = (const float*)d_in[6];
    float* out = (float*)d_out;

    k_reduce<<<M_ / 4, 256>>>((const float4*)x, (const float4*)Ws);
    k_att<<<B_, 256>>>(conv_w, conv_b);
    k_cvec<<<DIM_ / 8, 256>>>(bs, fc_w, fc_b);

    const int smem = 2 * (BM * LDA + BN * LDA) * (int)sizeof(float);  // 73728 B
    cudaFuncSetAttribute(k_gemm, cudaFuncAttributeMaxDynamicSharedMemorySize, smem);
    dim3 grid(DIM_ / BN, M_ / BM);        // (8, 16) = 128 CTAs, one wave
    k_gemm<<<grid, 256, smem>>>(fc_w, out);
}